// round 1
// baseline (speedup 1.0000x reference)
#include <cuda_runtime.h>

#define C_DIM 4096
#define N_F 8
#define NPAIR 36   // 8*9/2, i<=j
#define EPS_F 1e-8f

// Scratch accumulators (device globals; no allocation allowed).
__device__ float g_rowsum[N_F * C_DIM];   // rowsum[f][u] = sum_v a_f[u,v]
__device__ float g_cross[NPAIR];          // cross[i<=j] = sum_{u,v} a_i a_j

__device__ __forceinline__ float fsqrt_approx(float x) {
    float r;
    asm("sqrt.approx.f32 %0, %1;" : "=f"(r) : "f"(x));
    return r;
}

__global__ void zero_kernel() {
    int i = blockIdx.x * blockDim.x + threadIdx.x;
    for (; i < N_F * C_DIM; i += gridDim.x * blockDim.x) g_rowsum[i] = 0.0f;
    if (blockIdx.x == 0 && threadIdx.x < NPAIR) g_cross[threadIdx.x] = 0.0f;
}

// Grid: (16 u-tiles of 256, 32 v-chunks of 128). Block: 256 threads.
// Each thread owns one u, iterates 128 v's from shared memory.
__global__ __launch_bounds__(256) void pair_kernel(const float* __restrict__ x) {
    __shared__ float shv[128][N_F];           // [vi][f], 4 KB
    __shared__ float red[8][NPAIR];           // per-warp cross partials

    const int tid = threadIdx.x;
    const int u = blockIdx.x * 256 + tid;
    const int vbase = blockIdx.y * 128;

    // Load v-chunk of x into shared: coalesced over vi.
    for (int i = tid; i < 128 * N_F; i += 256) {
        int f = i >> 7;
        int vi = i & 127;
        shv[vi][f] = x[f * C_DIM + vbase + vi];
    }

    float xu[N_F];
#pragma unroll
    for (int f = 0; f < N_F; f++) xu[f] = x[f * C_DIM + u];

    __syncthreads();

    float rs[N_F];
    float acc[NPAIR];
#pragma unroll
    for (int f = 0; f < N_F; f++) rs[f] = 0.0f;
#pragma unroll
    for (int k = 0; k < NPAIR; k++) acc[k] = 0.0f;

#pragma unroll 2
    for (int vi = 0; vi < 128; vi++) {
        // Vectorized broadcast load of the 8 factor values at this v.
        float4 p0 = *reinterpret_cast<const float4*>(&shv[vi][0]);
        float4 p1 = *reinterpret_cast<const float4*>(&shv[vi][4]);
        float xv[N_F] = {p0.x, p0.y, p0.z, p0.w, p1.x, p1.y, p1.z, p1.w};

        float a[N_F];
#pragma unroll
        for (int f = 0; f < N_F; f++) {
            float d = xu[f] - xv[f];
            float t = fmaf(d, d, EPS_F);
            a[f] = fsqrt_approx(t);
            rs[f] += a[f];
        }

        int k = 0;
#pragma unroll
        for (int i = 0; i < N_F; i++) {
#pragma unroll
            for (int j = i; j < N_F; j++) {
                acc[k] = fmaf(a[i], a[j], acc[k]);
                k++;
            }
        }
    }

    // Row sums: u is unique within the block; accumulate across v-chunks via atomics.
#pragma unroll
    for (int f = 0; f < N_F; f++) atomicAdd(&g_rowsum[f * C_DIM + u], rs[f]);

    // Block-reduce the 36 cross accumulators, then one atomic per value.
    const int lane = tid & 31;
    const int warp = tid >> 5;
#pragma unroll
    for (int k = 0; k < NPAIR; k++) {
        float v = acc[k];
        for (int o = 16; o; o >>= 1) v += __shfl_down_sync(0xffffffffu, v, o);
        if (lane == 0) red[warp][k] = v;
    }
    __syncthreads();
    if (warp == 0) {
        for (int k = lane; k < NPAIR; k += 32) {
            float v = 0.0f;
#pragma unroll
            for (int w = 0; w < 8; w++) v += red[w][k];
            atomicAdd(&g_cross[k], v);
        }
    }
}

// Single block: 36 rowsum dot products + dcov/ratio math.
__global__ __launch_bounds__(256) void finalize_kernel(float* __restrict__ out) {
    const int tid = threadIdx.x;
    float dot[NPAIR];
    float ssum[N_F];
#pragma unroll
    for (int k = 0; k < NPAIR; k++) dot[k] = 0.0f;
#pragma unroll
    for (int f = 0; f < N_F; f++) ssum[f] = 0.0f;

    for (int u = tid; u < C_DIM; u += 256) {
        float r[N_F];
#pragma unroll
        for (int f = 0; f < N_F; f++) {
            r[f] = g_rowsum[f * C_DIM + u];
            ssum[f] += r[f];
        }
        int k = 0;
#pragma unroll
        for (int i = 0; i < N_F; i++) {
#pragma unroll
            for (int j = i; j < N_F; j++) {
                dot[k] = fmaf(r[i], r[j], dot[k]);
                k++;
            }
        }
    }

    __shared__ float stot[NPAIR + N_F];
    if (tid < NPAIR + N_F) stot[tid] = 0.0f;
    __syncthreads();

    const int lane = tid & 31;
#pragma unroll
    for (int k = 0; k < NPAIR; k++) {
        float v = dot[k];
        for (int o = 16; o; o >>= 1) v += __shfl_down_sync(0xffffffffu, v, o);
        if (lane == 0) atomicAdd(&stot[k], v);
    }
#pragma unroll
    for (int f = 0; f < N_F; f++) {
        float v = ssum[f];
        for (int o = 16; o; o >>= 1) v += __shfl_down_sync(0xffffffffu, v, o);
        if (lane == 0) atomicAdd(&stot[NPAIR + f], v);
    }
    __syncthreads();

    if (tid == 0) {
        const float fC = (float)C_DIM;
        const float invC2 = 1.0f / (fC * fC);

        float m[N_F];
#pragma unroll
        for (int f = 0; f < N_F; f++) m[f] = stot[NPAIR + f] * invC2;

        // S[i][j] = cross/C^2 - 2*(rowsum_i . rowsum_j)/C^3 + m_i*m_j
        // dcov    = sqrt(max(S,0)+eps)
        float dcov[N_F][N_F];
        int k = 0;
        for (int i = 0; i < N_F; i++) {
            for (int j = i; j < N_F; j++) {
                float s = g_cross[k] * invC2
                        - 2.0f * stot[k] * invC2 / fC
                        + m[i] * m[j];
                float dc = sqrtf(fmaxf(s, 0.0f) + EPS_F);
                dcov[i][j] = dc;
                dcov[j][i] = dc;
                k++;
            }
        }

        float cor = 0.0f;
        for (int i = 0; i < N_F; i++)
            for (int j = i + 1; j < N_F; j++)
                cor += dcov[i][j] / sqrtf(dcov[i][i] * dcov[j][j] + EPS_F);

        out[0] = cor;
    }
}

extern "C" void kernel_launch(void* const* d_in, const int* in_sizes, int n_in,
                              void* d_out, int out_size) {
    const float* x = (const float*)d_in[0];
    float* out = (float*)d_out;

    zero_kernel<<<32, 256>>>();
    pair_kernel<<<dim3(16, 32), 256>>>(x);
    finalize_kernel<<<1, 256>>>(out);
}